// round 1
// baseline (speedup 1.0000x reference)
#include <cuda_runtime.h>
#include <math.h>

#define B_   32
#define C_   768
#define D_   512
#define NH_  4
#define HD_  192
#define FHW_ 576

// ---------------- scratch (device globals; no runtime allocation) ------------
// layout (floats):
static const long OFF_T    = 0;                       // 32*512
static const long OFF_SQ   = OFF_T   + 32L*512;       // 32*4*192
static const long OFF_SK   = OFF_SQ  + 32L*4*192;
static const long OFF_MU1  = OFF_SK  + 32L*4*192;     // 18432
static const long OFF_RS1  = OFF_MU1 + 18432L;
static const long OFF_MU2  = OFF_RS1 + 18432L;
static const long OFF_RS2  = OFF_MU2 + 18432L;
static const long OFF_QKV  = OFF_RS2 + 18432L;        // 32*2304*576
static const long OFF_ATTN = OFF_QKV + 32L*2304*576;  // 32*4*192*576
static const long OFF_IMG  = OFF_ATTN+ 32L*4*192*576; // 32*768*192
static const long OFF_Y    = OFF_IMG + 32L*768*192;   // 32*768*576
static const long OFF_OUT  = OFF_Y   + 32L*768*576;
static const long OFF_Z1   = OFF_OUT + 32L*768*576;
static const long OFF_Z2   = OFF_Z1  + 32L*768*576;
static const long SCR_TOTAL= OFF_Z2  + 32L*768*576;

__device__ float g_scratch[SCR_TOTAL];

// ---------------- txt layernorm -----------------------------------------------
__global__ void txtln_k(const float* __restrict__ T, const float* __restrict__ gw,
                        const float* __restrict__ gb, float* __restrict__ Tn) {
    int b = blockIdx.x, tid = threadIdx.x;
    const float* row = T + (long)b * D_;
    float s = 0.f, ss = 0.f;
    for (int i = tid; i < D_; i += 256) { float v = row[i]; s += v; ss += v * v; }
    for (int o = 16; o; o >>= 1) { s += __shfl_down_sync(0xffffffffu, s, o); ss += __shfl_down_sync(0xffffffffu, ss, o); }
    __shared__ float red[16];
    __shared__ float mr[2];
    int w = tid >> 5;
    if ((tid & 31) == 0) { red[w] = s; red[8 + w] = ss; }
    __syncthreads();
    if (tid == 0) {
        float S = 0.f, S2 = 0.f;
        for (int i = 0; i < 8; i++) { S += red[i]; S2 += red[8 + i]; }
        float m = S / D_;
        float v = S2 / D_ - m * m;
        mr[0] = m; mr[1] = rsqrtf(v + 1e-5f);
    }
    __syncthreads();
    float m = mr[0], r = mr[1];
    for (int i = tid; i < D_; i += 256)
        Tn[(long)b * D_ + i] = (row[i] - m) * r * gw[i] + gb[i];
}

// ---------------- txt qkv projection -> sign factors --------------------------
__global__ void txtqkv_k(const float* __restrict__ Tn, const float* __restrict__ Wq,
                         float* __restrict__ sq, float* __restrict__ sk) {
    int b = blockIdx.x;
    __shared__ float t[512];
    for (int i = threadIdx.x; i < 512; i += 256) t[i] = Tn[(long)b * 512 + i];
    __syncthreads();
    int idx = blockIdx.y * 256 + threadIdx.x;     // 0..1535
    int n = idx / 384, r = idx % 384, part = r / 192, hd = r % 192;
    int o2 = n * 576 + part * 192 + hd;           // reshape (NH,3,HD)
    const float* w = Wq + (long)o2 * 512;
    float acc = 0.f;
    #pragma unroll 8
    for (int k2 = 0; k2 < 512; k2++) acc += t[k2] * w[k2];
    float sgn = acc / fmaxf(fabsf(acc), 1e-12f);
    if (part == 0) sq[(b * 4 + n) * 192 + hd] = sgn;
    else           sk[(b * 4 + n) * 192 + hd] = sgn;
}

// ---------------- per-pixel layernorm stats over C ----------------------------
__global__ void stats_k(const float* __restrict__ X, float* __restrict__ mu,
                        float* __restrict__ rs, float eps) {
    int px0 = blockIdx.x * 32;
    int lane = threadIdx.x & 31, grp = threadIdx.x >> 5;
    int gp = px0 + lane;
    int b = gp / FHW_, p = gp % FHW_;
    const float* base = X + (long)b * C_ * FHW_ + p;
    float s = 0.f, ss = 0.f;
    for (int c = grp; c < C_; c += 8) { float v = base[(long)c * FHW_]; s += v; ss += v * v; }
    __shared__ float Ss[8][32], S2[8][32];
    Ss[grp][lane] = s; S2[grp][lane] = ss;
    __syncthreads();
    if (grp == 0) {
        for (int g = 1; g < 8; g++) { s += Ss[g][lane]; ss += S2[g][lane]; }
        float m = s / C_;
        float v = ss / C_ - m * m;
        mu[gp] = m;
        rs[gp] = rsqrtf(v + eps);
    }
}

// ---------------- generic tiled SGEMM -----------------------------------------
// C[m,n] = sum_k A[m,k] * B[k,n]  (batched via blockIdx.z)
enum { BMODE_PLAIN = 0, BMODE_LN = 1, BMODE_TRANS = 2 };
enum { EPI_NONE = 0, EPI_BIASM = 1, EPI_BIASN = 2, EPI_BIASM_RES = 3, EPI_RES = 4 };

template<int BM, int BN, int BK, int TM, int TN, int BMODE, int EPI>
__global__ void __launch_bounds__(256)
gemm_k(const float* __restrict__ A, const float* __restrict__ Bp, float* __restrict__ Cp,
       int M, int N, int K,
       long sA, long sBout, int divB, long sBin, long sC,
       const float* __restrict__ mu, const float* __restrict__ rs,
       const float* __restrict__ lw, const float* __restrict__ lb,
       const float* __restrict__ biasM, const float* __restrict__ biasN,
       const float* __restrict__ res, long sRes)
{
    static_assert((BM / TM) * (BN / TN) == 256, "thread grid");
    const int bz = blockIdx.z;
    const long offA = sA * bz;
    const long offB = (long)(bz / divB) * sBout + (long)(bz % divB) * sBin;
    const long offC = sC * bz;
    const int n0 = blockIdx.x * BN;
    const int m0 = blockIdx.y * BM;
    const int tid = threadIdx.x;
    const int TXN = BN / TN;
    const int tx = tid % TXN;
    const int ty = tid / TXN;

    __shared__ __align__(16) float As[BK][BM];
    __shared__ __align__(16) float Bs[BK][BN];
    __shared__ float muS[BN], rsS[BN];

    if (BMODE == BMODE_LN) {
        for (int i = tid; i < BN; i += 256) {
            muS[i] = mu[(long)bz * N + n0 + i];
            rsS[i] = rs[(long)bz * N + n0 + i];
        }
        __syncthreads();
    }

    float acc[TM][TN];
    #pragma unroll
    for (int i = 0; i < TM; i++)
        #pragma unroll
        for (int j = 0; j < TN; j++) acc[i][j] = 0.f;

    const int LA = BM * BK / 256;
    const int LB = BK * BN / 256;

    for (int kb = 0; kb < K; kb += BK) {
        #pragma unroll
        for (int i = 0; i < LA; i++) {
            int idx = tid + i * 256;
            int am = idx / BK, ak = idx % BK;
            As[ak][am] = A[offA + (long)(m0 + am) * K + kb + ak];
        }
        if (BMODE == BMODE_TRANS) {
            #pragma unroll
            for (int i = 0; i < LB; i++) {
                int idx = tid + i * 256;
                int bn = idx / BK, bk = idx % BK;
                Bs[bk][bn] = Bp[offB + (long)(n0 + bn) * K + kb + bk];
            }
        } else {
            #pragma unroll
            for (int i = 0; i < LB; i++) {
                int idx = tid + i * 256;
                int bk = idx / BN, bn = idx % BN;
                float x = Bp[offB + (long)(kb + bk) * N + n0 + bn];
                if (BMODE == BMODE_LN) {
                    int c = kb + bk;
                    x = lw[c] * ((x - muS[bn]) * rsS[bn]) + lb[c];
                }
                Bs[bk][bn] = x;
            }
        }
        __syncthreads();

        #pragma unroll
        for (int kk = 0; kk < BK; kk++) {
            float a[TM], bb[TN];
            const float4* ap = reinterpret_cast<const float4*>(&As[kk][ty * TM]);
            #pragma unroll
            for (int i = 0; i < TM / 4; i++) {
                float4 v = ap[i];
                a[4*i] = v.x; a[4*i+1] = v.y; a[4*i+2] = v.z; a[4*i+3] = v.w;
            }
            const float4* bp4 = reinterpret_cast<const float4*>(&Bs[kk][tx * TN]);
            #pragma unroll
            for (int j = 0; j < TN / 4; j++) {
                float4 v = bp4[j];
                bb[4*j] = v.x; bb[4*j+1] = v.y; bb[4*j+2] = v.z; bb[4*j+3] = v.w;
            }
            #pragma unroll
            for (int i = 0; i < TM; i++)
                #pragma unroll
                for (int j = 0; j < TN; j++)
                    acc[i][j] = fmaf(a[i], bb[j], acc[i][j]);
        }
        __syncthreads();
    }

    #pragma unroll
    for (int i = 0; i < TM; i++) {
        int row = m0 + ty * TM + i;
        #pragma unroll
        for (int j = 0; j < TN; j++) {
            int col = n0 + tx * TN + j;
            float v = acc[i][j];
            if (EPI == EPI_BIASM || EPI == EPI_BIASM_RES) v += biasM[row];
            if (EPI == EPI_BIASN) v += biasN[col];
            if (EPI == EPI_BIASM_RES || EPI == EPI_RES)
                v += res[sRes * bz + (long)row * N + col];
            Cp[offC + (long)row * N + col] = v;
        }
    }
}

// ---------------- fused attention rows: softmax(±k/|k|)+softmax(±q/|q|) -------
__device__ __forceinline__ float blockReduce192(float v, int op, float* sh) {
    for (int o = 16; o; o >>= 1) {
        float t = __shfl_down_sync(0xffffffffu, v, o);
        v = op ? fmaxf(v, t) : v + t;
    }
    int w = threadIdx.x >> 5;
    if ((threadIdx.x & 31) == 0) sh[w] = v;
    __syncthreads();
    float r = sh[0];
    for (int i = 1; i < 6; i++) r = op ? fmaxf(r, sh[i]) : r + sh[i];
    __syncthreads();
    return r;
}

__global__ void attn_k(const float* __restrict__ qkv, const float* __restrict__ sq,
                       const float* __restrict__ sk, float* __restrict__ attn) {
    int bid = blockIdx.x;                 // b*768 + n*192 + hd
    int hd = bid % 192, n = (bid / 192) % 4, b = bid / 768;
    const float* qrow = qkv + ((long)b * 2304 + n * 192 + hd) * 576;
    const float* krow = qrow + 768L * 576;
    int tid = threadIdx.x;                // 192 threads, 3 elems each
    float q0 = qrow[tid], q1 = qrow[tid + 192], q2 = qrow[tid + 384];
    float k0 = krow[tid], k1 = krow[tid + 192], k2 = krow[tid + 384];

    __shared__ float sh[6];
    float sumq = blockReduce192(q0*q0 + q1*q1 + q2*q2, 0, sh);
    float sumk = blockReduce192(k0*k0 + k1*k1 + k2*k2, 0, sh);
    float rq = 1.f / fmaxf(sqrtf(sumq), 1e-12f);
    float rk = 1.f / fmaxf(sqrtf(sumk), 1e-12f);
    float sgq = sq[(b * 4 + n) * 192 + hd];
    float sgk = sk[(b * 4 + n) * 192 + hd];

    float a0 = sgq * k0 * rk, a1 = sgq * k1 * rk, a2 = sgq * k2 * rk;
    float c0 = sgk * q0 * rq, c1 = sgk * q1 * rq, c2 = sgk * q2 * rq;

    float M1 = blockReduce192(fmaxf(a0, fmaxf(a1, a2)), 1, sh);
    float e0 = __expf(a0 - M1), e1 = __expf(a1 - M1), e2 = __expf(a2 - M1);
    float S1 = blockReduce192(e0 + e1 + e2, 0, sh);

    float M2 = blockReduce192(fmaxf(c0, fmaxf(c1, c2)), 1, sh);
    float f0 = __expf(c0 - M2), f1 = __expf(c1 - M2), f2 = __expf(c2 - M2);
    float S2 = blockReduce192(f0 + f1 + f2, 0, sh);

    float i1 = 1.f / S1, i2 = 1.f / S2;
    float* o = attn + ((long)(b * 4 + n) * 192 + hd) * 576;
    o[tid]       = e0 * i1 + f0 * i2;
    o[tid + 192] = e1 * i1 + f1 * i2;
    o[tid + 384] = e2 * i1 + f2 * i2;
}

// ---------------- depthwise 3x3 conv + exact GELU -----------------------------
__global__ void dwgelu_k(const float* __restrict__ Z, const float* __restrict__ Wd,
                         float* __restrict__ O) {
    int bc = blockIdx.x;                  // b*768 + c
    int c = bc % 768;
    __shared__ float p[576];
    const float* base = Z + (long)bc * 576;
    for (int i = threadIdx.x; i < 576; i += 256) p[i] = base[i];
    float w[9];
    #pragma unroll
    for (int i = 0; i < 9; i++) w[i] = Wd[c * 9 + i];
    __syncthreads();
    for (int i = threadIdx.x; i < 576; i += 256) {
        int y = i / 24, x = i % 24;
        float acc = 0.f;
        #pragma unroll
        for (int dy = -1; dy <= 1; dy++)
            #pragma unroll
            for (int dx = -1; dx <= 1; dx++) {
                int yy = y + dy, xx = x + dx;
                if (yy >= 0 && yy < 24 && xx >= 0 && xx < 24)
                    acc = fmaf(w[(dy + 1) * 3 + dx + 1], p[yy * 24 + xx], acc);
            }
        O[(long)bc * 576 + i] = 0.5f * acc * (1.f + erff(acc * 0.70710678118654752f));
    }
}

// ---------------- host launch --------------------------------------------------
extern "C" void kernel_launch(void* const* d_in, const int* in_sizes, int n_in,
                              void* d_out, int out_size) {
    const float* img    = (const float*)d_in[0];
    const float* txt    = (const float*)d_in[1];
    const float* fn_w   = (const float*)d_in[2];
    const float* fn_b   = (const float*)d_in[3];
    const float* gn_w   = (const float*)d_in[4];
    const float* gn_b   = (const float*)d_in[5];
    const float* qkv_img_w = (const float*)d_in[6];
    const float* qkv_txt_w = (const float*)d_in[7];
    const float* o_img_w   = (const float*)d_in[8];
    const float* o_img_b   = (const float*)d_in[9];
    const float* o_img2_w  = (const float*)d_in[10];
    const float* o_img2_b  = (const float*)d_in[11];
    const float* ffn_w  = (const float*)d_in[12];
    const float* ffn_b  = (const float*)d_in[13];
    const float* fc1_w  = (const float*)d_in[14];
    const float* dw_w   = (const float*)d_in[15];
    const float* fc2_w  = (const float*)d_in[16];
    float* out_p = (float*)d_out;

    float* scr = nullptr;
    cudaGetSymbolAddress((void**)&scr, g_scratch);
    float* tbuf = scr + OFF_T;
    float* sqb  = scr + OFF_SQ;
    float* skb  = scr + OFF_SK;
    float* mu1  = scr + OFF_MU1;
    float* rs1  = scr + OFF_RS1;
    float* mu2  = scr + OFF_MU2;
    float* rs2  = scr + OFF_RS2;
    float* qkvb = scr + OFF_QKV;
    float* attnb= scr + OFF_ATTN;
    float* imgb = scr + OFF_IMG;
    float* yb   = scr + OFF_Y;
    float* outb = scr + OFF_OUT;
    float* z1   = scr + OFF_Z1;
    float* z2   = scr + OFF_Z2;

    const long sFeat = (long)C_ * FHW_;      // 442368
    const long sQKV  = 3L * C_ * FHW_;       // 1327104
    const long sAttn = (long)HD_ * FHW_;     // 110592
    const long sImg  = (long)C_ * HD_;       // 147456

    // 1. txt layernorm
    txtln_k<<<32, 256>>>(txt, gn_w, gn_b, tbuf);
    // 2. txt qkv -> sign factors
    txtqkv_k<<<dim3(32, 6), 256>>>(tbuf, qkv_txt_w, sqb, skb);
    // 3. img layernorm stats
    stats_k<<<(B_ * FHW_) / 32, 256>>>(img, mu1, rs1, 1e-6f);
    // 4. qkv projection with fused layernorm (M=2304,N=576,K=768, b=32)
    gemm_k<128, 64, 16, 8, 4, BMODE_LN, EPI_NONE><<<dim3(9, 18, 32), 256>>>(
        qkv_img_w, img, qkvb, 3 * C_, FHW_, C_,
        0, sFeat, 1, 0, sQKV,
        mu1, rs1, fn_w, fn_b, nullptr, nullptr, nullptr, 0);
    // 5. attention rows: summed softmax matrices
    attn_k<<<B_ * NH_ * HD_, 192>>>(qkvb, sqb, skb, attnb);
    // 6. (attn1+attn2) @ V^T  (M=192,N=192,K=576, batch=128)
    gemm_k<64, 64, 16, 4, 4, BMODE_TRANS, EPI_NONE><<<dim3(3, 3, 128), 256>>>(
        attnb, qkvb + 2L * C_ * FHW_, imgb, HD_, HD_, FHW_,
        sAttn, sQKV, 4, sAttn, (long)HD_ * HD_,
        nullptr, nullptr, nullptr, nullptr, nullptr, nullptr, nullptr, 0);
    // 7. img @ o_img2_w^T + b2  (M=768,N=576,K=192, b=32)
    gemm_k<128, 64, 16, 8, 4, BMODE_TRANS, EPI_BIASN><<<dim3(9, 6, 32), 256>>>(
        imgb, o_img2_w, yb, C_, FHW_, HD_,
        sImg, 0, 1, 0, sFeat,
        nullptr, nullptr, nullptr, nullptr, nullptr, o_img2_b, nullptr, 0);
    // 8. o_img conv1x1 + bias + residual(img)  -> out
    gemm_k<128, 64, 16, 8, 4, BMODE_PLAIN, EPI_BIASM_RES><<<dim3(9, 6, 32), 256>>>(
        o_img_w, yb, outb, C_, FHW_, C_,
        0, sFeat, 1, 0, sFeat,
        nullptr, nullptr, nullptr, nullptr, o_img_b, nullptr, img, sFeat);
    // 9. ffn layernorm stats on out
    stats_k<<<(B_ * FHW_) / 32, 256>>>(outb, mu2, rs2, 1e-6f);
    // 10. fc1 with fused layernorm
    gemm_k<128, 64, 16, 8, 4, BMODE_LN, EPI_NONE><<<dim3(9, 6, 32), 256>>>(
        fc1_w, outb, z1, C_, FHW_, C_,
        0, sFeat, 1, 0, sFeat,
        mu2, rs2, ffn_w, ffn_b, nullptr, nullptr, nullptr, 0);
    // 11. depthwise 3x3 + exact gelu
    dwgelu_k<<<B_ * C_, 256>>>(z1, dw_w, z2);
    // 12. fc2 + residual(out) -> d_out
    gemm_k<128, 64, 16, 8, 4, BMODE_PLAIN, EPI_RES><<<dim3(9, 6, 32), 256>>>(
        fc2_w, z2, out_p, C_, FHW_, C_,
        0, sFeat, 1, 0, sFeat,
        nullptr, nullptr, nullptr, nullptr, nullptr, nullptr, outb, sFeat);
}